// round 3
// baseline (speedup 1.0000x reference)
#include <cuda_runtime.h>

#define BB   4
#define CC_  64
#define HH   96
#define WW   96
#define HW_  (HH*WW)
#define CHW_ (CC_*HW_)

// ---------------- scratch (static device globals; no allocation) ----------------
__device__ float g_smooth[BB*CHW_];
__device__ float g_sup2  [BB*CHW_];
__device__ float g_v     [3*BB*CHW_];
__device__ float g_agg   [3*BB*CHW_];

// shift table: sh in (-3,0,3) x sw in (-3,0,3) minus (0,0)
__constant__ int c_sh[8] = {-3,-3,-3, 0, 0, 3, 3, 3};
__constant__ int c_sw[8] = {-3, 0, 3,-3, 3,-3, 0, 3};

// ---------------- kernel 1: shift + grouped 3x3 conv (smooth) ----------------
__global__ __launch_bounds__(256) void smooth_kernel(
    const float* __restrict__ sup, const float* __restrict__ w,
    const float* __restrict__ bias, float* __restrict__ out)
{
    __shared__ float s_in[8*18*18];
    __shared__ float s_w [8*8*9];

    int bz = blockIdx.z;
    int g  = bz & 7;
    int b  = bz >> 3;
    int x0 = blockIdx.x * 16, y0 = blockIdx.y * 16;
    int sh = c_sh[g], sw = c_sw[g];
    int tid = threadIdx.x;

    // conv input at shifted-space position (sy,sx):
    //   0 if (sy,sx) outside image (conv's own padding=1 ring)
    //   else shifted(sy,sx) = sup(sy-sh, sx-sw) zero-padded (shift <= pad, no wrap)
    for (int e = tid; e < 8*324; e += 256) {
        int ci = e / 324, rem = e % 324;
        int rr = rem / 18, cc = rem % 18;
        int sy = y0 - 1 + rr;
        int sx = x0 - 1 + cc;
        int gy = sy - sh;
        int gx = sx - sw;
        float v = 0.f;
        if (sy >= 0 && sy < HH && sx >= 0 && sx < WW &&
            gy >= 0 && gy < HH && gx >= 0 && gx < WW)
            v = sup[b*CHW_ + (g*8 + ci)*HW_ + gy*WW + gx];
        s_in[e] = v;
    }
    for (int e = tid; e < 576; e += 256) s_w[e] = w[g*8*72 + e]; // [co][ci][tap]
    __syncthreads();

    int ty = tid >> 4, tx = tid & 15;
    float acc[8];
    #pragma unroll
    for (int j = 0; j < 8; j++) acc[j] = 0.f;

    #pragma unroll 1
    for (int ci = 0; ci < 8; ci++) {
        const float* base = s_in + ci*324 + ty*18 + tx;
        #pragma unroll
        for (int t = 0; t < 9; t++) {
            int dy = t / 3, dx = t % 3;
            float v = base[dy*18 + dx];
            #pragma unroll
            for (int co = 0; co < 8; co++)
                acc[co] = fmaf(s_w[co*72 + ci*9 + t], v, acc[co]);
        }
    }
    int y = y0 + ty, x = x0 + tx;
    #pragma unroll
    for (int co = 0; co < 8; co++)
        out[b*CHW_ + (g*8 + co)*HW_ + y*WW + x] = acc[co] + bias[g*8 + co];
}

// ---------------- kernel 2: pointwise conv (1x1), CIN in {64,128} ----------------
// block: 256 px of one batch, 64 co; thread: 4 px x 16 co
template<int CIN>
__global__ __launch_bounds__(256) void pw_kernel(
    const float* __restrict__ inA, const float* __restrict__ inB,
    const float* __restrict__ wgt, const float* __restrict__ bias,
    float* __restrict__ out)
{
    __shared__ float s_in[16*256];
    __shared__ float s_w [64*16];

    int b  = blockIdx.y;
    int p0 = blockIdx.x * 256;
    int tid = threadIdx.x;
    int pl = tid & 63;
    int cg = tid >> 6;

    float acc[4][16];
    #pragma unroll
    for (int k = 0; k < 4; k++)
        #pragma unroll
        for (int j = 0; j < 16; j++) acc[k][j] = 0.f;

    for (int c0 = 0; c0 < CIN; c0 += 16) {
        #pragma unroll
        for (int i = 0; i < 16; i++) {
            int e  = tid + i*256;
            int ci = c0 + (e >> 8);
            int px = e & 255;
            const float* src;
            if (CIN == 64 || ci < 64) src = inA + b*CHW_ + ci*HW_;
            else                      src = inB + b*CHW_ + (ci - 64)*HW_;
            s_in[e] = src[p0 + px];
        }
        #pragma unroll
        for (int i = 0; i < 4; i++) {
            int e = tid + i*256;
            int co = e >> 4, ci = e & 15;
            s_w[e] = wgt[co*CIN + c0 + ci];
        }
        __syncthreads();

        #pragma unroll 4
        for (int ci = 0; ci < 16; ci++) {
            float v0 = s_in[ci*256 + pl];
            float v1 = s_in[ci*256 + pl + 64];
            float v2 = s_in[ci*256 + pl + 128];
            float v3 = s_in[ci*256 + pl + 192];
            #pragma unroll
            for (int j = 0; j < 16; j++) {
                float wv = s_w[(cg*16 + j)*16 + ci];
                acc[0][j] = fmaf(wv, v0, acc[0][j]);
                acc[1][j] = fmaf(wv, v1, acc[1][j]);
                acc[2][j] = fmaf(wv, v2, acc[2][j]);
                acc[3][j] = fmaf(wv, v3, acc[3][j]);
            }
        }
        __syncthreads();
    }

    #pragma unroll
    for (int j = 0; j < 16; j++) {
        int co = cg*16 + j;
        float bv = bias[co];
        float* o = out + b*CHW_ + co*HW_ + p0;
        o[pl]       = acc[0][j] + bv;
        o[pl + 64]  = acc[1][j] + bv;
        o[pl + 128] = acc[2][j] + bv;
        o[pl + 192] = acc[3][j] + bv;
    }
}

// ---------------- kernel 3: fused NATTEN level (qk + bias + softmax + av) ----------------
// tile 16(x) x 8(y), 128 threads, one pixel each. k/v tiles + rpb + logit staging in smem.
template<int KS>
__global__ __launch_bounds__(128) void natten_kernel(
    const float* __restrict__ q, const float* __restrict__ k,
    const float* __restrict__ v, const float* __restrict__ rpb,
    float* __restrict__ out)
{
    constexpr int R   = KS/2;
    constexpr int YR  = 8  + 2*R;
    constexpr int XR  = 16 + 2*R;
    constexpr int KSQ = KS*KS;
    constexpr int RPB = 2*KS - 1;

    extern __shared__ float sm[];
    float* s_k   = sm;
    float* s_v   = s_k + 64*YR*XR;
    float* s_rpb = s_v + 64*YR*XR;
    float* s_att = s_rpb + RPB*RPB;     // 128 * KSQ (KSQ odd -> conflict free)

    int b  = blockIdx.z;
    int x0 = blockIdx.x * 16;
    int y0 = blockIdx.y * 8;
    int tid = threadIdx.x;

    const float* kb = k + b*CHW_;
    const float* vb = v + b*CHW_;
    for (int e = tid; e < 64*YR*XR; e += 128) {
        int c   = e / (YR*XR);
        int rem = e % (YR*XR);
        int yy  = rem / XR, xx = rem % XR;
        int gy  = y0 - R + yy, gx = x0 - R + xx;
        float kv = 0.f, vv = 0.f;
        if (gy >= 0 && gy < HH && gx >= 0 && gx < WW) {
            kv = kb[c*HW_ + gy*WW + gx];
            vv = vb[c*HW_ + gy*WW + gx];
        }
        s_k[e] = kv; s_v[e] = vv;
    }
    for (int e = tid; e < RPB*RPB; e += 128) s_rpb[e] = rpb[e];
    __syncthreads();

    int ty = tid >> 4, tx = tid & 15;
    int y = y0 + ty, x = x0 + tx;

    float qr[64];
    #pragma unroll
    for (int c = 0; c < 64; c++) qr[c] = q[b*CHW_ + c*HW_ + y*WW + x];

    int ni = min(max(y - R, 0), HH - KS);
    int nj = min(max(x - R, 0), WW - KS);
    int yy0 = ni - (y0 - R);
    int xx0 = nj - (x0 - R);
    int pi  = KS - 1 + ni - y;
    int pj  = KS - 1 + nj - x;

    float mx = -1e30f;
    int n = 0;
    #pragma unroll 1
    for (int p = 0; p < KS; p++) {
        #pragma unroll 1
        for (int qq = 0; qq < KS; qq++, n++) {
            const float* kp = s_k + (yy0 + p)*XR + xx0 + qq;
            float d0 = 0.f, d1 = 0.f, d2 = 0.f, d3 = 0.f;
            #pragma unroll
            for (int c = 0; c < 64; c += 4) {
                d0 = fmaf(qr[c],     kp[(c  )*YR*XR], d0);
                d1 = fmaf(qr[c + 1], kp[(c+1)*YR*XR], d1);
                d2 = fmaf(qr[c + 2], kp[(c+2)*YR*XR], d2);
                d3 = fmaf(qr[c + 3], kp[(c+3)*YR*XR], d3);
            }
            float dot = (d0 + d1) + (d2 + d3) + s_rpb[(pi + p)*RPB + pj + qq];
            s_att[tid*KSQ + n] = dot;
            mx = fmaxf(mx, dot);
        }
    }

    float ar[KSQ];
    float ssum = 0.f;
    #pragma unroll
    for (int m = 0; m < KSQ; m++) {
        float e = __expf(s_att[tid*KSQ + m] - mx);
        ar[m] = e;
        ssum += e;
    }
    float inv = 1.0f / ssum;
    #pragma unroll
    for (int m = 0; m < KSQ; m++) ar[m] *= inv;

    float* ob = out + b*CHW_ + y*WW + x;
    #pragma unroll 1
    for (int c = 0; c < 64; c++) {
        const float* vp = s_v + c*YR*XR + yy0*XR + xx0;
        float a0 = 0.f;
        #pragma unroll
        for (int p = 0; p < KS; p++)
            #pragma unroll
            for (int qq = 0; qq < KS; qq++)
                a0 = fmaf(ar[p*KS + qq], vp[p*XR + qq], a0);
        ob[c*HW_] = a0;
    }
}

// ---------------- kernel 4: fusion 3x3 conv (256 -> 64) + ReLU ----------------
// block: 16x16 px tile of one batch, 64 co; thread: 4 px x 16 co (64 accumulators)
__global__ __launch_bounds__(256) void fusion_kernel(
    const float* __restrict__ sup, const float* __restrict__ agg,
    const float* __restrict__ fw,  const float* __restrict__ fb,
    float* __restrict__ out)
{
    extern __shared__ float smf[];
    float* s_in = smf;            // 16 * 18 * 18
    float* s_w  = smf + 16*324;   // 64 * 144 (global layout [co][ci16*9])

    int b  = blockIdx.z;
    int x0 = blockIdx.x * 16, y0 = blockIdx.y * 16;
    int tid = threadIdx.x;
    int pl  = tid & 63;           // pixel lane
    int cg  = tid >> 6;           // co group (16 co each)
    int tyb = pl >> 4, tx0 = pl & 15;  // base pixel row 0..3

    float acc[4][16];
    #pragma unroll
    for (int k = 0; k < 4; k++)
        #pragma unroll
        for (int j = 0; j < 16; j++) acc[k][j] = 0.f;

    #pragma unroll 1
    for (int src = 0; src < 4; src++) {
        const float* ip = (src == 0) ? (sup + b*CHW_)
                                     : (agg + (src - 1)*(BB*CHW_) + b*CHW_);
        #pragma unroll 1
        for (int c0 = 0; c0 < 64; c0 += 16) {
            for (int e = tid; e < 16*324; e += 256) {
                int ci  = e / 324, rem = e % 324;
                int rr  = rem / 18, cc = rem % 18;
                int gy  = y0 - 1 + rr, gx = x0 - 1 + cc;
                float vv = 0.f;
                if (gy >= 0 && gy < HH && gx >= 0 && gx < WW)
                    vv = ip[(c0 + ci)*HW_ + gy*WW + gx];
                s_in[e] = vv;
            }
            int cinb = src*64 + c0;
            for (int e = tid; e < 64*144; e += 256) {
                int co = e / 144, rem = e % 144;
                s_w[e] = fw[co*2304 + cinb*9 + rem];
            }
            __syncthreads();

            #pragma unroll 1
            for (int ci = 0; ci < 16; ci++) {
                const float* wp = s_w + (cg*16)*144 + ci*9;
                const float* i0 = s_in + ci*324 + tyb*18 + tx0;
                #pragma unroll
                for (int t = 0; t < 9; t++) {
                    int dy = t / 3, dx = t % 3;
                    float v0 = i0[(dy     )*18 + dx];
                    float v1 = i0[(dy + 4 )*18 + dx];
                    float v2 = i0[(dy + 8 )*18 + dx];
                    float v3 = i0[(dy + 12)*18 + dx];
                    #pragma unroll
                    for (int j = 0; j < 16; j++) {
                        float wv = wp[j*144 + t];
                        acc[0][j] = fmaf(wv, v0, acc[0][j]);
                        acc[1][j] = fmaf(wv, v1, acc[1][j]);
                        acc[2][j] = fmaf(wv, v2, acc[2][j]);
                        acc[3][j] = fmaf(wv, v3, acc[3][j]);
                    }
                }
            }
            __syncthreads();
        }
    }

    #pragma unroll
    for (int j = 0; j < 16; j++) {
        int co = cg*16 + j;
        float bv = fb[co];
        #pragma unroll
        for (int kk = 0; kk < 4; kk++) {
            float r = acc[kk][j] + bv;
            r = (r > 0.f) ? r : 0.f;
            out[b*CHW_ + co*HW_ + (y0 + tyb + 4*kk)*WW + x0 + tx0] = r;
        }
    }
}

// ---------------- launch ----------------
static int natten_smem_bytes(int ks) {
    int r  = ks/2;
    int yr = 8 + 2*r, xr = 16 + 2*r;
    return (2*64*yr*xr + (2*ks - 1)*(2*ks - 1) + 128*ks*ks) * 4;
}

extern "C" void kernel_launch(void* const* d_in, const int* in_sizes, int n_in,
                              void* d_out, int out_size)
{
    const float* sup = (const float*)d_in[0];
    const float* key = (const float*)d_in[1];
    const float* csw = (const float*)d_in[2];
    const float* csb = (const float*)d_in[3];
    const float* crw = (const float*)d_in[4];
    const float* crb = (const float*)d_in[5];

    const float *vw[3], *vb[3], *rpb[3];
    if (in_sizes[8] == 25) {
        // dict-insertion (interleaved) order: v_w0, v_b0, rpb0, v_w1, v_b1, rpb1, ...
        for (int l = 0; l < 3; l++) {
            vw[l]  = (const float*)d_in[6 + 3*l];
            vb[l]  = (const float*)d_in[7 + 3*l];
            rpb[l] = (const float*)d_in[8 + 3*l];
        }
    } else {
        // signature order: v_w0, v_b0, v_w1, v_b1, v_w2, v_b2, rpb0, rpb1, rpb2
        for (int l = 0; l < 3; l++) {
            vw[l]  = (const float*)d_in[6 + 2*l];
            vb[l]  = (const float*)d_in[7 + 2*l];
            rpb[l] = (const float*)d_in[12 + l];
        }
    }
    const float* fw = (const float*)d_in[15];
    const float* fb = (const float*)d_in[16];
    float* out = (float*)d_out;

    float *smoothp, *sup2p, *vp, *aggp;
    cudaGetSymbolAddress((void**)&smoothp, g_smooth);
    cudaGetSymbolAddress((void**)&sup2p,   g_sup2);
    cudaGetSymbolAddress((void**)&vp,      g_v);
    cudaGetSymbolAddress((void**)&aggp,    g_agg);

    // opt-in smem (idempotent, deterministic; attribute persists on the function)
    cudaFuncSetAttribute(natten_kernel<3>, cudaFuncAttributeMaxDynamicSharedMemorySize, natten_smem_bytes(3));
    cudaFuncSetAttribute(natten_kernel<5>, cudaFuncAttributeMaxDynamicSharedMemorySize, natten_smem_bytes(5));
    cudaFuncSetAttribute(natten_kernel<7>, cudaFuncAttributeMaxDynamicSharedMemorySize, natten_smem_bytes(7));
    cudaFuncSetAttribute(fusion_kernel,    cudaFuncAttributeMaxDynamicSharedMemorySize, (16*324 + 64*144)*4);

    // 1. spatial shift + grouped smooth conv
    smooth_kernel<<<dim3(6, 6, BB*8), 256>>>(sup, csw, csb, smoothp);

    // 2. sup2 = 1x1 reduce over concat(sup, smooth)
    pw_kernel<128><<<dim3(HW_/256, BB), 256>>>(sup, smoothp, crw, crb, sup2p);

    // 3. per-level v conv then fused NATTEN
    for (int lvl = 0; lvl < 3; lvl++)
        pw_kernel<64><<<dim3(HW_/256, BB), 256>>>(sup2p, nullptr, vw[lvl], vb[lvl],
                                                  vp + lvl*(BB*CHW_));
    natten_kernel<3><<<dim3(6, 12, BB), 128, natten_smem_bytes(3)>>>(
        key, sup2p, vp + 0*(BB*CHW_), rpb[0], aggp + 0*(BB*CHW_));
    natten_kernel<5><<<dim3(6, 12, BB), 128, natten_smem_bytes(5)>>>(
        key, sup2p, vp + 1*(BB*CHW_), rpb[1], aggp + 1*(BB*CHW_));
    natten_kernel<7><<<dim3(6, 12, BB), 128, natten_smem_bytes(7)>>>(
        key, sup2p, vp + 2*(BB*CHW_), rpb[2], aggp + 2*(BB*CHW_));

    // 4. fusion 3x3 + ReLU
    fusion_kernel<<<dim3(6, 6, BB), 256, (16*324 + 64*144)*4>>>(sup, aggp, fw, fb, out);
}

// round 7
// speedup vs baseline: 1.0620x; 1.0620x over previous
#include <cuda_runtime.h>

#define BB   4
#define CC_  64
#define HH   96
#define WW   96
#define HW_  (HH*WW)
#define CHW_ (CC_*HW_)

typedef unsigned long long ull;

// ---------------- packed f32x2 helpers ----------------
__device__ __forceinline__ ull pack2(float x, float y) {
    ull r; asm("mov.b64 %0, {%1, %2};" : "=l"(r) : "f"(x), "f"(y)); return r;
}
__device__ __forceinline__ float2 unpack2(ull v) {
    float2 t; asm("mov.b64 {%0, %1}, %2;" : "=f"(t.x), "=f"(t.y) : "l"(v)); return t;
}
__device__ __forceinline__ ull lds64f(const float* p) {
    ull r;
    asm("ld.shared.b64 %0, [%1];" : "=l"(r)
        : "l"((ull)__cvta_generic_to_shared(p)));
    return r;
}
__device__ __forceinline__ void fma2(ull& d, ull a, ull b) {
    asm("fma.rn.f32x2 %0, %1, %2, %0;" : "+l"(d) : "l"(a), "l"(b));
}

// ---------------- scratch (static device globals; no allocation) ----------------
__device__ float g_smooth[BB*CHW_];
__device__ float g_sup2  [BB*CHW_];
__device__ float g_v     [3*BB*CHW_];
__device__ float g_agg   [3*BB*CHW_];

// shift table: sh in (-3,0,3) x sw in (-3,0,3) minus (0,0)
__constant__ int c_sh[8] = {-3,-3,-3, 0, 0, 3, 3, 3};
__constant__ int c_sw[8] = {-3, 0, 3,-3, 3,-3, 0, 3};

// ---------------- kernel 1: shift + grouped 3x3 conv (smooth) ----------------
__global__ __launch_bounds__(256) void smooth_kernel(
    const float* __restrict__ sup, const float* __restrict__ w,
    const float* __restrict__ bias, float* __restrict__ out)
{
    __shared__ float s_in[8*18*18];
    __shared__ float s_w [8*8*9];

    int bz = blockIdx.z;
    int g  = bz & 7;
    int b  = bz >> 3;
    int x0 = blockIdx.x * 16, y0 = blockIdx.y * 16;
    int sh = c_sh[g], sw = c_sw[g];
    int tid = threadIdx.x;

    // conv input at shifted-space (sy,sx): 0 outside image (conv pad ring),
    // else sup(sy-sh, sx-sw) zero-padded
    for (int e = tid; e < 8*324; e += 256) {
        int ci = e / 324, rem = e % 324;
        int rr = rem / 18, cc = rem % 18;
        int sy = y0 - 1 + rr;
        int sx = x0 - 1 + cc;
        int gy = sy - sh;
        int gx = sx - sw;
        float v = 0.f;
        if (sy >= 0 && sy < HH && sx >= 0 && sx < WW &&
            gy >= 0 && gy < HH && gx >= 0 && gx < WW)
            v = sup[b*CHW_ + (g*8 + ci)*HW_ + gy*WW + gx];
        s_in[e] = v;
    }
    for (int e = tid; e < 576; e += 256) s_w[e] = w[g*8*72 + e];
    __syncthreads();

    int ty = tid >> 4, tx = tid & 15;
    float acc[8];
    #pragma unroll
    for (int j = 0; j < 8; j++) acc[j] = 0.f;

    #pragma unroll 1
    for (int ci = 0; ci < 8; ci++) {
        const float* base = s_in + ci*324 + ty*18 + tx;
        #pragma unroll
        for (int t = 0; t < 9; t++) {
            int dy = t / 3, dx = t % 3;
            float v = base[dy*18 + dx];
            #pragma unroll
            for (int co = 0; co < 8; co++)
                acc[co] = fmaf(s_w[co*72 + ci*9 + t], v, acc[co]);
        }
    }
    int y = y0 + ty, x = x0 + tx;
    #pragma unroll
    for (int co = 0; co < 8; co++)
        out[b*CHW_ + (g*8 + co)*HW_ + y*WW + x] = acc[co] + bias[g*8 + co];
}

// ---------------- kernel 2a: pointwise conv 1x1, CIN=128 ----------------
__global__ __launch_bounds__(256) void pw128_kernel(
    const float* __restrict__ inA, const float* __restrict__ inB,
    const float* __restrict__ wgt, const float* __restrict__ bias,
    float* __restrict__ out)
{
    __shared__ float s_in[16*256];
    __shared__ float s_w [64*16];

    int b  = blockIdx.y;
    int p0 = blockIdx.x * 256;
    int tid = threadIdx.x;
    int pl = tid & 63;
    int cg = tid >> 6;

    float acc[4][16];
    #pragma unroll
    for (int k = 0; k < 4; k++)
        #pragma unroll
        for (int j = 0; j < 16; j++) acc[k][j] = 0.f;

    for (int c0 = 0; c0 < 128; c0 += 16) {
        #pragma unroll
        for (int i = 0; i < 16; i++) {
            int e  = tid + i*256;
            int ci = c0 + (e >> 8);
            int px = e & 255;
            const float* src = (ci < 64) ? (inA + b*CHW_ + ci*HW_)
                                         : (inB + b*CHW_ + (ci - 64)*HW_);
            s_in[e] = src[p0 + px];
        }
        #pragma unroll
        for (int i = 0; i < 4; i++) {
            int e = tid + i*256;
            int co = e >> 4, ci = e & 15;
            s_w[e] = wgt[co*128 + c0 + ci];
        }
        __syncthreads();

        #pragma unroll 4
        for (int ci = 0; ci < 16; ci++) {
            float v0 = s_in[ci*256 + pl];
            float v1 = s_in[ci*256 + pl + 64];
            float v2 = s_in[ci*256 + pl + 128];
            float v3 = s_in[ci*256 + pl + 192];
            #pragma unroll
            for (int j = 0; j < 16; j++) {
                float wv = s_w[(cg*16 + j)*16 + ci];
                acc[0][j] = fmaf(wv, v0, acc[0][j]);
                acc[1][j] = fmaf(wv, v1, acc[1][j]);
                acc[2][j] = fmaf(wv, v2, acc[2][j]);
                acc[3][j] = fmaf(wv, v3, acc[3][j]);
            }
        }
        __syncthreads();
    }

    #pragma unroll
    for (int j = 0; j < 16; j++) {
        int co = cg*16 + j;
        float bv = bias[co];
        float* o = out + b*CHW_ + co*HW_ + p0;
        o[pl]       = acc[0][j] + bv;
        o[pl + 64]  = acc[1][j] + bv;
        o[pl + 128] = acc[2][j] + bv;
        o[pl + 192] = acc[3][j] + bv;
    }
}

// ---------------- kernel 2b: three 1x1 convs (64->64) in one launch ----------------
// grid.y encodes (lvl, b): lvl = blockIdx.y >> 2, b = blockIdx.y & 3
__global__ __launch_bounds__(256) void pw64x3_kernel(
    const float* __restrict__ inA,
    const float* __restrict__ w0, const float* __restrict__ b0,
    const float* __restrict__ w1, const float* __restrict__ b1,
    const float* __restrict__ w2, const float* __restrict__ b2,
    float* __restrict__ out)
{
    __shared__ float s_in[16*256];
    __shared__ float s_w [64*16];

    int lvl = blockIdx.y >> 2;
    int b   = blockIdx.y & 3;
    const float* wgt  = (lvl == 0) ? w0 : (lvl == 1) ? w1 : w2;
    const float* bias = (lvl == 0) ? b0 : (lvl == 1) ? b1 : b2;
    out += lvl * (BB*CHW_);

    int p0 = blockIdx.x * 256;
    int tid = threadIdx.x;
    int pl = tid & 63;
    int cg = tid >> 6;

    float acc[4][16];
    #pragma unroll
    for (int k = 0; k < 4; k++)
        #pragma unroll
        for (int j = 0; j < 16; j++) acc[k][j] = 0.f;

    for (int c0 = 0; c0 < 64; c0 += 16) {
        #pragma unroll
        for (int i = 0; i < 16; i++) {
            int e  = tid + i*256;
            int ci = c0 + (e >> 8);
            int px = e & 255;
            s_in[e] = inA[b*CHW_ + ci*HW_ + p0 + px];
        }
        #pragma unroll
        for (int i = 0; i < 4; i++) {
            int e = tid + i*256;
            int co = e >> 4, ci = e & 15;
            s_w[e] = wgt[co*64 + c0 + ci];
        }
        __syncthreads();

        #pragma unroll 4
        for (int ci = 0; ci < 16; ci++) {
            float v0 = s_in[ci*256 + pl];
            float v1 = s_in[ci*256 + pl + 64];
            float v2 = s_in[ci*256 + pl + 128];
            float v3 = s_in[ci*256 + pl + 192];
            #pragma unroll
            for (int j = 0; j < 16; j++) {
                float wv = s_w[(cg*16 + j)*16 + ci];
                acc[0][j] = fmaf(wv, v0, acc[0][j]);
                acc[1][j] = fmaf(wv, v1, acc[1][j]);
                acc[2][j] = fmaf(wv, v2, acc[2][j]);
                acc[3][j] = fmaf(wv, v3, acc[3][j]);
            }
        }
        __syncthreads();
    }

    #pragma unroll
    for (int j = 0; j < 16; j++) {
        int co = cg*16 + j;
        float bv = bias[co];
        float* o = out + b*CHW_ + co*HW_ + p0;
        o[pl]       = acc[0][j] + bv;
        o[pl + 64]  = acc[1][j] + bv;
        o[pl + 128] = acc[2][j] + bv;
        o[pl + 192] = acc[3][j] + bv;
    }
}

// ---------------- kernel 3: fused NATTEN level, packed channel pairs ----------------
// tile 16(x) x 8(y), 128 threads, one pixel each.
// k/v stored interleaved: [c2][y][x] float2 (channel pair contiguous).
template<int KS>
__global__ __launch_bounds__(128) void natten_kernel(
    const float* __restrict__ q, const float* __restrict__ k,
    const float* __restrict__ v, const float* __restrict__ rpb,
    float* __restrict__ out)
{
    constexpr int R    = KS/2;
    constexpr int YR   = 8  + 2*R;
    constexpr int XR   = 16 + 2*R;
    constexpr int TILE = YR*XR;
    constexpr int KSQ  = KS*KS;
    constexpr int RPB  = 2*KS - 1;

    extern __shared__ float sm[];
    float* s_k   = sm;                  // 64*TILE floats (32 pairs)
    float* s_v   = s_k + 64*TILE;
    float* s_rpb = s_v + 64*TILE;
    float* s_att = s_rpb + RPB*RPB;     // 128 * KSQ (KSQ odd -> conflict free)

    int b  = blockIdx.z;
    int x0 = blockIdx.x * 16;
    int y0 = blockIdx.y * 8;
    int tid = threadIdx.x;

    const float* kb = k + b*CHW_;
    const float* vb = v + b*CHW_;
    for (int e = tid; e < 32*TILE; e += 128) {
        int c2  = e / TILE;
        int rem = e % TILE;
        int yy  = rem / XR, xx = rem % XR;
        int gy  = y0 - R + yy, gx = x0 - R + xx;
        float k0 = 0.f, k1 = 0.f, v0 = 0.f, v1 = 0.f;
        if (gy >= 0 && gy < HH && gx >= 0 && gx < WW) {
            int base = (2*c2)*HW_ + gy*WW + gx;
            k0 = kb[base]; k1 = kb[base + HW_];
            v0 = vb[base]; v1 = vb[base + HW_];
        }
        s_k[2*e] = k0; s_k[2*e + 1] = k1;
        s_v[2*e] = v0; s_v[2*e + 1] = v1;
    }
    for (int e = tid; e < RPB*RPB; e += 128) s_rpb[e] = rpb[e];
    __syncthreads();

    int ty = tid >> 4, tx = tid & 15;
    int y = y0 + ty, x = x0 + tx;

    ull q2[32];
    #pragma unroll
    for (int c2 = 0; c2 < 32; c2++) {
        const float* qp = q + b*CHW_ + (2*c2)*HW_ + y*WW + x;
        q2[c2] = pack2(qp[0], qp[HW_]);
    }

    int ni = min(max(y - R, 0), HH - KS);
    int nj = min(max(x - R, 0), WW - KS);
    int yy0 = ni - (y0 - R);
    int xx0 = nj - (x0 - R);
    int pi  = KS - 1 + ni - y;
    int pj  = KS - 1 + nj - x;

    float mx = -1e30f;
    #pragma unroll 1
    for (int p = 0; p < KS; p++) {
        #pragma unroll 1
        for (int qq = 0; qq < KS; qq++) {
            const float* kp = s_k + 2*((yy0 + p)*XR + xx0 + qq);
            ull s0 = 0ull, s1 = 0ull, s2 = 0ull, s3 = 0ull;
            #pragma unroll
            for (int c2 = 0; c2 < 32; c2 += 4) {
                fma2(s0, q2[c2],     lds64f(kp + 2*(c2    )*TILE));
                fma2(s1, q2[c2 + 1], lds64f(kp + 2*(c2 + 1)*TILE));
                fma2(s2, q2[c2 + 2], lds64f(kp + 2*(c2 + 2)*TILE));
                fma2(s3, q2[c2 + 3], lds64f(kp + 2*(c2 + 3)*TILE));
            }
            float2 ua = unpack2(s0), ub = unpack2(s1);
            float2 uc = unpack2(s2), ud = unpack2(s3);
            float dot = ((ua.x + ua.y) + (ub.x + ub.y))
                      + ((uc.x + uc.y) + (ud.x + ud.y))
                      + s_rpb[(pi + p)*RPB + pj + qq];
            s_att[tid*KSQ + p*KS + qq] = dot;
            mx = fmaxf(mx, dot);
        }
    }

    // softmax: exp into s_att, keep 1/sum to fold later
    float ssum = 0.f;
    #pragma unroll 1
    for (int m = 0; m < KSQ; m++) {
        float e = __expf(s_att[tid*KSQ + m] - mx);
        s_att[tid*KSQ + m] = e;
        ssum += e;
    }
    float inv = 1.0f / ssum;

    // AV: two halves of 16 channel-pairs, tap-outer
    float* ob = out + b*CHW_ + y*WW + x;
    #pragma unroll 1
    for (int h = 0; h < 2; h++) {
        ull accv[16];
        #pragma unroll
        for (int i = 0; i < 16; i++) accv[i] = 0ull;
        #pragma unroll 1
        for (int t = 0; t < KSQ; t++) {
            int p = t / KS, qq = t % KS;
            const float* vp = s_v + 2*((h*16)*TILE + (yy0 + p)*XR + xx0 + qq);
            float av = s_att[tid*KSQ + t] * inv;
            ull a2 = pack2(av, av);
            #pragma unroll
            for (int i = 0; i < 16; i++)
                fma2(accv[i], a2, lds64f(vp + 2*i*TILE));
        }
        #pragma unroll
        for (int i = 0; i < 16; i++) {
            float2 rv = unpack2(accv[i]);
            int c = 2*(h*16 + i);
            ob[c*HW_]       = rv.x;
            ob[(c + 1)*HW_] = rv.y;
        }
    }
}

// ---------------- kernel 4: fusion 3x3 conv (256 -> 64) + ReLU, f32x2 ----------------
// block: 16x16 px tile; thread: 4 x-adjacent px (quad) x 16 co, packed pairs.
__global__ __launch_bounds__(256) void fusion_kernel(
    const float* __restrict__ sup, const float* __restrict__ agg,
    const float* __restrict__ fw,  const float* __restrict__ fb,
    float* __restrict__ out)
{
    extern __shared__ float smf[];
    float* s_in = smf;            // 16 ci x 18 rows x stride 20 = 5760
    float* s_w2 = smf + 5760;     // 64 co x 144 duplicated pairs = 18432

    int b  = blockIdx.z;
    int x0 = blockIdx.x * 16, y0 = blockIdx.y * 16;
    int tid = threadIdx.x;
    int pl  = tid & 63;
    int cg  = tid >> 6;
    int r   = pl >> 2;            // output row 0..15
    int qd  = pl & 3;             // x-quad: pixels x0+qd*4 .. +3

    ull acc[2][16];
    #pragma unroll
    for (int kk = 0; kk < 2; kk++)
        #pragma unroll
        for (int j = 0; j < 16; j++) acc[kk][j] = 0ull;

    #pragma unroll 1
    for (int src = 0; src < 4; src++) {
        const float* ip = (src == 0) ? (sup + b*CHW_)
                                     : (agg + (src - 1)*(BB*CHW_) + b*CHW_);
        #pragma unroll 1
        for (int c0 = 0; c0 < 64; c0 += 16) {
            for (int e = tid; e < 16*324; e += 256) {
                int ci  = e / 324, rem = e % 324;
                int rr  = rem / 18, cc = rem % 18;
                int gy  = y0 - 1 + rr, gx = x0 - 1 + cc;
                float vv = 0.f;
                if (gy >= 0 && gy < HH && gx >= 0 && gx < WW)
                    vv = ip[(c0 + ci)*HW_ + gy*WW + gx];
                s_in[ci*360 + rr*20 + cc] = vv;
            }
            int cinb = src*64 + c0;
            for (int e = tid; e < 64*144; e += 256) {
                int co = e / 144, rem = e % 144;
                float wv = fw[co*2304 + cinb*9 + rem];
                s_w2[2*e] = wv; s_w2[2*e + 1] = wv;
            }
            __syncthreads();

            #pragma unroll 1
            for (int ci = 0; ci < 16; ci++) {
                const float* row = s_in + ci*360 + r*20 + qd*4;
                #pragma unroll
                for (int dy = 0; dy < 3; dy++) {
                    float2 P0 = *(const float2*)(row + dy*20 + 0); // i0,i1
                    float2 P1 = *(const float2*)(row + dy*20 + 2); // i2,i3
                    float2 P2 = *(const float2*)(row + dy*20 + 4); // i4,i5
                    ull A0 = pack2(P0.x, P0.y), B0 = pack2(P1.x, P1.y);
                    ull A1 = pack2(P0.y, P1.x), B1 = pack2(P1.y, P2.x);
                    ull A2 = B0,                B2 = pack2(P2.x, P2.y);
                    const float* wp = s_w2 + ((cg*16)*144 + ci*9 + dy*3)*2;
                    #pragma unroll
                    for (int j = 0; j < 16; j++) {
                        ull w0 = lds64f(wp + j*288 + 0);
                        fma2(acc[0][j], w0, A0);
                        fma2(acc[1][j], w0, B0);
                        ull w1 = lds64f(wp + j*288 + 2);
                        fma2(acc[0][j], w1, A1);
                        fma2(acc[1][j], w1, B1);
                        ull w2 = lds64f(wp + j*288 + 4);
                        fma2(acc[0][j], w2, A2);
                        fma2(acc[1][j], w2, B2);
                    }
                }
            }
            __syncthreads();
        }
    }

    int y = y0 + r, xb = x0 + qd*4;
    #pragma unroll
    for (int j = 0; j < 16; j++) {
        int co = cg*16 + j;
        float bv = fb[co];
        float2 lo = unpack2(acc[0][j]);
        float2 hi = unpack2(acc[1][j]);
        float4 o;
        o.x = fmaxf(lo.x + bv, 0.f);
        o.y = fmaxf(lo.y + bv, 0.f);
        o.z = fmaxf(hi.x + bv, 0.f);
        o.w = fmaxf(hi.y + bv, 0.f);
        *(float4*)&out[b*CHW_ + co*HW_ + y*WW + xb] = o;
    }
}

// ---------------- launch ----------------
static int natten_smem_bytes(int ks) {
    int r  = ks/2;
    int yr = 8 + 2*r, xr = 16 + 2*r;
    return (2*64*yr*xr + (2*ks - 1)*(2*ks - 1) + 128*ks*ks) * 4;
}

extern "C" void kernel_launch(void* const* d_in, const int* in_sizes, int n_in,
                              void* d_out, int out_size)
{
    const float* sup = (const float*)d_in[0];
    const float* key = (const float*)d_in[1];
    const float* csw = (const float*)d_in[2];
    const float* csb = (const float*)d_in[3];
    const float* crw = (const float*)d_in[4];
    const float* crb = (const float*)d_in[5];

    const float *vw[3], *vb[3], *rpb[3];
    if (in_sizes[8] == 25) {
        // dict-insertion (interleaved): v_w0, v_b0, rpb0, v_w1, v_b1, rpb1, ...
        for (int l = 0; l < 3; l++) {
            vw[l]  = (const float*)d_in[6 + 3*l];
            vb[l]  = (const float*)d_in[7 + 3*l];
            rpb[l] = (const float*)d_in[8 + 3*l];
        }
    } else {
        // signature order
        for (int l = 0; l < 3; l++) {
            vw[l]  = (const float*)d_in[6 + 2*l];
            vb[l]  = (const float*)d_in[7 + 2*l];
            rpb[l] = (const float*)d_in[12 + l];
        }
    }
    const float* fw = (const float*)d_in[15];
    const float* fb = (const float*)d_in[16];
    float* out = (float*)d_out;

    float *smoothp, *sup2p, *vp, *aggp;
    cudaGetSymbolAddress((void**)&smoothp, g_smooth);
    cudaGetSymbolAddress((void**)&sup2p,   g_sup2);
    cudaGetSymbolAddress((void**)&vp,      g_v);
    cudaGetSymbolAddress((void**)&aggp,    g_agg);

    cudaFuncSetAttribute(natten_kernel<3>, cudaFuncAttributeMaxDynamicSharedMemorySize, natten_smem_bytes(3));
    cudaFuncSetAttribute(natten_kernel<5>, cudaFuncAttributeMaxDynamicSharedMemorySize, natten_smem_bytes(5));
    cudaFuncSetAttribute(natten_kernel<7>, cudaFuncAttributeMaxDynamicSharedMemorySize, natten_smem_bytes(7));
    cudaFuncSetAttribute(fusion_kernel,    cudaFuncAttributeMaxDynamicSharedMemorySize, (5760 + 18432)*4);

    // 1. spatial shift + grouped smooth conv
    smooth_kernel<<<dim3(6, 6, BB*8), 256>>>(sup, csw, csb, smoothp);

    // 2. sup2 = 1x1 reduce over concat(sup, smooth)
    pw128_kernel<<<dim3(HW_/256, BB), 256>>>(sup, smoothp, crw, crb, sup2p);

    // 3. all three v convs in one launch, then fused NATTEN per level
    pw64x3_kernel<<<dim3(HW_/256, BB*3), 256>>>(sup2p,
        vw[0], vb[0], vw[1], vb[1], vw[2], vb[2], vp);

    natten_kernel<3><<<dim3(6, 12, BB), 128, natten_smem_bytes(3)>>>(
        key, sup2p, vp + 0*(BB*CHW_), rpb[0], aggp + 0*(BB*CHW_));
    natten_kernel<5><<<dim3(6, 12, BB), 128, natten_smem_bytes(5)>>>(
        key, sup2p, vp + 1*(BB*CHW_), rpb[1], aggp + 1*(BB*CHW_));
    natten_kernel<7><<<dim3(6, 12, BB), 128, natten_smem_bytes(7)>>>(
        key, sup2p, vp + 2*(BB*CHW_), rpb[2], aggp + 2*(BB*CHW_));

    // 4. fusion 3x3 + ReLU (packed f32x2)
    fusion_kernel<<<dim3(6, 6, BB), 256, (5760 + 18432)*4>>>(sup, aggp, fw, fb, out);
}

// round 9
// speedup vs baseline: 1.1711x; 1.1028x over previous
#include <cuda_runtime.h>

#define BB   4
#define CC_  64
#define HH   96
#define WW   96
#define HW_  (HH*WW)
#define CHW_ (CC_*HW_)

typedef unsigned long long ull;

// ---------------- packed f32x2 helpers ----------------
__device__ __forceinline__ ull pack2(float x, float y) {
    ull r; asm("mov.b64 %0, {%1, %2};" : "=l"(r) : "f"(x), "f"(y)); return r;
}
__device__ __forceinline__ float2 unpack2(ull v) {
    float2 t; asm("mov.b64 {%0, %1}, %2;" : "=f"(t.x), "=f"(t.y) : "l"(v)); return t;
}
__device__ __forceinline__ ull lds64f(const float* p) {
    ull r;
    asm("ld.shared.b64 %0, [%1];" : "=l"(r)
        : "l"((ull)__cvta_generic_to_shared(p)));
    return r;
}
__device__ __forceinline__ void fma2(ull& d, ull a, ull b) {
    asm("fma.rn.f32x2 %0, %1, %2, %0;" : "+l"(d) : "l"(a), "l"(b));
}

// ---------------- scratch (static device globals; no allocation) ----------------
__device__ float g_smooth[BB*CHW_];
__device__ float g_sup2  [BB*CHW_];
__device__ float g_v     [3*BB*CHW_];
__device__ float g_agg   [3*BB*CHW_];

// shift table: sh in (-3,0,3) x sw in (-3,0,3) minus (0,0)
__constant__ int c_sh[8] = {-3,-3,-3, 0, 0, 3, 3, 3};
__constant__ int c_sw[8] = {-3, 0, 3,-3, 3,-3, 0, 3};

// ---------------- kernel 1: shift + grouped 3x3 conv (smooth) ----------------
__global__ __launch_bounds__(256) void smooth_kernel(
    const float* __restrict__ sup, const float* __restrict__ w,
    const float* __restrict__ bias, float* __restrict__ out)
{
    __shared__ float s_in[8*18*18];
    __shared__ float s_w [8*8*9];

    int bz = blockIdx.z;
    int g  = bz & 7;
    int b  = bz >> 3;
    int x0 = blockIdx.x * 16, y0 = blockIdx.y * 16;
    int sh = c_sh[g], sw = c_sw[g];
    int tid = threadIdx.x;

    // conv input at shifted-space (sy,sx): 0 outside image (conv pad ring),
    // else sup(sy-sh, sx-sw) zero-padded
    for (int e = tid; e < 8*324; e += 256) {
        int ci = e / 324, rem = e % 324;
        int rr = rem / 18, cc = rem % 18;
        int sy = y0 - 1 + rr;
        int sx = x0 - 1 + cc;
        int gy = sy - sh;
        int gx = sx - sw;
        float v = 0.f;
        if (sy >= 0 && sy < HH && sx >= 0 && sx < WW &&
            gy >= 0 && gy < HH && gx >= 0 && gx < WW)
            v = sup[b*CHW_ + (g*8 + ci)*HW_ + gy*WW + gx];
        s_in[e] = v;
    }
    for (int e = tid; e < 576; e += 256) s_w[e] = w[g*8*72 + e];
    __syncthreads();

    int ty = tid >> 4, tx = tid & 15;
    float acc[8];
    #pragma unroll
    for (int j = 0; j < 8; j++) acc[j] = 0.f;

    #pragma unroll 1
    for (int ci = 0; ci < 8; ci++) {
        const float* base = s_in + ci*324 + ty*18 + tx;
        #pragma unroll
        for (int t = 0; t < 9; t++) {
            int dy = t / 3, dx = t % 3;
            float v = base[dy*18 + dx];
            #pragma unroll
            for (int co = 0; co < 8; co++)
                acc[co] = fmaf(s_w[co*72 + ci*9 + t], v, acc[co]);
        }
    }
    int y = y0 + ty, x = x0 + tx;
    #pragma unroll
    for (int co = 0; co < 8; co++)
        out[b*CHW_ + (g*8 + co)*HW_ + y*WW + x] = acc[co] + bias[g*8 + co];
}

// ---------------- kernel 2a: pointwise conv 1x1, CIN=128 ----------------
__global__ __launch_bounds__(256) void pw128_kernel(
    const float* __restrict__ inA, const float* __restrict__ inB,
    const float* __restrict__ wgt, const float* __restrict__ bias,
    float* __restrict__ out)
{
    __shared__ float s_in[16*256];
    __shared__ float s_w [64*16];

    int b  = blockIdx.y;
    int p0 = blockIdx.x * 256;
    int tid = threadIdx.x;
    int pl = tid & 63;
    int cg = tid >> 6;

    float acc[4][16];
    #pragma unroll
    for (int k = 0; k < 4; k++)
        #pragma unroll
        for (int j = 0; j < 16; j++) acc[k][j] = 0.f;

    for (int c0 = 0; c0 < 128; c0 += 16) {
        #pragma unroll
        for (int i = 0; i < 16; i++) {
            int e  = tid + i*256;
            int ci = c0 + (e >> 8);
            int px = e & 255;
            const float* src = (ci < 64) ? (inA + b*CHW_ + ci*HW_)
                                         : (inB + b*CHW_ + (ci - 64)*HW_);
            s_in[e] = src[p0 + px];
        }
        #pragma unroll
        for (int i = 0; i < 4; i++) {
            int e = tid + i*256;
            int co = e >> 4, ci = e & 15;
            s_w[e] = wgt[co*128 + c0 + ci];
        }
        __syncthreads();

        #pragma unroll 4
        for (int ci = 0; ci < 16; ci++) {
            float v0 = s_in[ci*256 + pl];
            float v1 = s_in[ci*256 + pl + 64];
            float v2 = s_in[ci*256 + pl + 128];
            float v3 = s_in[ci*256 + pl + 192];
            #pragma unroll
            for (int j = 0; j < 16; j++) {
                float wv = s_w[(cg*16 + j)*16 + ci];
                acc[0][j] = fmaf(wv, v0, acc[0][j]);
                acc[1][j] = fmaf(wv, v1, acc[1][j]);
                acc[2][j] = fmaf(wv, v2, acc[2][j]);
                acc[3][j] = fmaf(wv, v3, acc[3][j]);
            }
        }
        __syncthreads();
    }

    #pragma unroll
    for (int j = 0; j < 16; j++) {
        int co = cg*16 + j;
        float bv = bias[co];
        float* o = out + b*CHW_ + co*HW_ + p0;
        o[pl]       = acc[0][j] + bv;
        o[pl + 64]  = acc[1][j] + bv;
        o[pl + 128] = acc[2][j] + bv;
        o[pl + 192] = acc[3][j] + bv;
    }
}

// ---------------- kernel 2b: three 1x1 convs (64->64) in one launch ----------------
__global__ __launch_bounds__(256) void pw64x3_kernel(
    const float* __restrict__ inA,
    const float* __restrict__ w0, const float* __restrict__ b0,
    const float* __restrict__ w1, const float* __restrict__ b1,
    const float* __restrict__ w2, const float* __restrict__ b2,
    float* __restrict__ out)
{
    __shared__ float s_in[16*256];
    __shared__ float s_w [64*16];

    int lvl = blockIdx.y >> 2;
    int b   = blockIdx.y & 3;
    const float* wgt  = (lvl == 0) ? w0 : (lvl == 1) ? w1 : w2;
    const float* bias = (lvl == 0) ? b0 : (lvl == 1) ? b1 : b2;
    out += lvl * (BB*CHW_);

    int p0 = blockIdx.x * 256;
    int tid = threadIdx.x;
    int pl = tid & 63;
    int cg = tid >> 6;

    float acc[4][16];
    #pragma unroll
    for (int k = 0; k < 4; k++)
        #pragma unroll
        for (int j = 0; j < 16; j++) acc[k][j] = 0.f;

    for (int c0 = 0; c0 < 64; c0 += 16) {
        #pragma unroll
        for (int i = 0; i < 16; i++) {
            int e  = tid + i*256;
            int ci = c0 + (e >> 8);
            int px = e & 255;
            s_in[e] = inA[b*CHW_ + ci*HW_ + p0 + px];
        }
        #pragma unroll
        for (int i = 0; i < 4; i++) {
            int e = tid + i*256;
            int co = e >> 4, ci = e & 15;
            s_w[e] = wgt[co*64 + c0 + ci];
        }
        __syncthreads();

        #pragma unroll 4
        for (int ci = 0; ci < 16; ci++) {
            float v0 = s_in[ci*256 + pl];
            float v1 = s_in[ci*256 + pl + 64];
            float v2 = s_in[ci*256 + pl + 128];
            float v3 = s_in[ci*256 + pl + 192];
            #pragma unroll
            for (int j = 0; j < 16; j++) {
                float wv = s_w[(cg*16 + j)*16 + ci];
                acc[0][j] = fmaf(wv, v0, acc[0][j]);
                acc[1][j] = fmaf(wv, v1, acc[1][j]);
                acc[2][j] = fmaf(wv, v2, acc[2][j]);
                acc[3][j] = fmaf(wv, v3, acc[3][j]);
            }
        }
        __syncthreads();
    }

    #pragma unroll
    for (int j = 0; j < 16; j++) {
        int co = cg*16 + j;
        float bv = bias[co];
        float* o = out + b*CHW_ + co*HW_ + p0;
        o[pl]       = acc[0][j] + bv;
        o[pl + 64]  = acc[1][j] + bv;
        o[pl + 128] = acc[2][j] + bv;
        o[pl + 192] = acc[3][j] + bv;
    }
}

// ---------------- kernel 3: fused NATTEN, channel-split, 256 threads ----------------
// tile 16(x) x 8(y); thread (h, px): h = warp-half (channels h*32..h*32+31),
// px = pixel. QK partials staged in s_part[2][128][KSQ]; half-0 warps finish
// softmax and write normalized weights back; both halves do AV on own channels.
template<int KS>
__global__ __launch_bounds__(256) void natten_kernel(
    const float* __restrict__ q, const float* __restrict__ k,
    const float* __restrict__ v, const float* __restrict__ rpb,
    float* __restrict__ out)
{
    constexpr int R    = KS/2;
    constexpr int YR   = 8  + 2*R;
    constexpr int XR   = 16 + 2*R;
    constexpr int TILE = YR*XR;
    constexpr int KSQ  = KS*KS;
    constexpr int RPB  = 2*KS - 1;

    extern __shared__ float sm[];
    float* s_k    = sm;                   // 64*TILE floats (32 c2-pairs)
    float* s_v    = s_k + 64*TILE;
    float* s_rpb  = s_v + 64*TILE;
    float* s_part = s_rpb + RPB*RPB;      // [2][128][KSQ]

    int b  = blockIdx.z;
    int x0 = blockIdx.x * 16;
    int y0 = blockIdx.y * 8;
    int tid = threadIdx.x;
    int h   = tid >> 7;
    int px  = tid & 127;

    const float* kb = k + b*CHW_;
    const float* vb = v + b*CHW_;
    for (int e = tid; e < 32*TILE; e += 256) {
        int c2  = e / TILE;
        int rem = e % TILE;
        int yy  = rem / XR, xx = rem % XR;
        int gy  = y0 - R + yy, gx = x0 - R + xx;
        float k0 = 0.f, k1 = 0.f, v0 = 0.f, v1 = 0.f;
        if (gy >= 0 && gy < HH && gx >= 0 && gx < WW) {
            int base = (2*c2)*HW_ + gy*WW + gx;
            k0 = kb[base]; k1 = kb[base + HW_];
            v0 = vb[base]; v1 = vb[base + HW_];
        }
        s_k[2*e] = k0; s_k[2*e + 1] = k1;
        s_v[2*e] = v0; s_v[2*e + 1] = v1;
    }
    for (int e = tid; e < RPB*RPB; e += 256) s_rpb[e] = rpb[e];
    __syncthreads();

    int ty = px >> 4, tx = px & 15;
    int y = y0 + ty, x = x0 + tx;

    // q registers for this half's 16 channel-pairs
    ull q2[16];
    #pragma unroll
    for (int i = 0; i < 16; i++) {
        int c2 = h*16 + i;
        const float* qp = q + b*CHW_ + (2*c2)*HW_ + y*WW + x;
        q2[i] = pack2(qp[0], qp[HW_]);
    }

    int ni = min(max(y - R, 0), HH - KS);
    int nj = min(max(x - R, 0), WW - KS);
    int yy0 = ni - (y0 - R);
    int xx0 = nj - (x0 - R);
    int pi  = KS - 1 + ni - y;
    int pj  = KS - 1 + nj - x;

    // QK partial dots over this half's 32 channels
    #pragma unroll 1
    for (int p = 0; p < KS; p++) {
        #pragma unroll 1
        for (int qq = 0; qq < KS; qq++) {
            const float* kp = s_k + 2*((h*16)*TILE + (yy0 + p)*XR + xx0 + qq);
            ull s0 = 0ull, s1 = 0ull, s2 = 0ull, s3 = 0ull;
            #pragma unroll
            for (int i = 0; i < 16; i += 4) {
                fma2(s0, q2[i],     lds64f(kp + 2*(i    )*TILE));
                fma2(s1, q2[i + 1], lds64f(kp + 2*(i + 1)*TILE));
                fma2(s2, q2[i + 2], lds64f(kp + 2*(i + 2)*TILE));
                fma2(s3, q2[i + 3], lds64f(kp + 2*(i + 3)*TILE));
            }
            float2 ua = unpack2(s0), ub = unpack2(s1);
            float2 uc = unpack2(s2), ud = unpack2(s3);
            s_part[h*128*KSQ + px*KSQ + p*KS + qq] =
                ((ua.x + ua.y) + (ub.x + ub.y)) + ((uc.x + uc.y) + (ud.x + ud.y));
        }
    }
    __syncthreads();

    // half-0 warps: combine partials + rpb, softmax, write normalized weights
    if (h == 0) {
        float ar[KSQ];
        float mx = -1e30f;
        #pragma unroll
        for (int t = 0; t < KSQ; t++) {
            int p = t / KS, qq = t % KS;
            float dot = s_part[px*KSQ + t] + s_part[128*KSQ + px*KSQ + t]
                      + s_rpb[(pi + p)*RPB + pj + qq];
            ar[t] = dot;
            mx = fmaxf(mx, dot);
        }
        float ssum = 0.f;
        #pragma unroll
        for (int t = 0; t < KSQ; t++) {
            float e = __expf(ar[t] - mx);
            ar[t] = e;
            ssum += e;
        }
        float inv = 1.0f / ssum;
        #pragma unroll
        for (int t = 0; t < KSQ; t++)
            s_part[px*KSQ + t] = ar[t] * inv;
    }
    __syncthreads();

    // AV over this half's 16 channel-pairs
    ull accv[16];
    #pragma unroll
    for (int i = 0; i < 16; i++) accv[i] = 0ull;
    #pragma unroll 1
    for (int t = 0; t < KSQ; t++) {
        int p = t / KS, qq = t % KS;
        const float* vp = s_v + 2*((h*16)*TILE + (yy0 + p)*XR + xx0 + qq);
        float av = s_part[px*KSQ + t];
        ull a2 = pack2(av, av);
        #pragma unroll
        for (int i = 0; i < 16; i++)
            fma2(accv[i], a2, lds64f(vp + 2*i*TILE));
    }
    float* ob = out + b*CHW_ + y*WW + x;
    #pragma unroll
    for (int i = 0; i < 16; i++) {
        float2 rv = unpack2(accv[i]);
        int c = 2*(h*16 + i);
        ob[c*HW_]       = rv.x;
        ob[(c + 1)*HW_] = rv.y;
    }
}

// ---------------- kernel 4: fusion 3x3 conv (256 -> 64) + ReLU, f32x2, 512 thr ----
// block: 16x16 px tile; thread: 4 x-adjacent px (quad) x 8 co, packed pairs.
__global__ __launch_bounds__(512) void fusion_kernel(
    const float* __restrict__ sup, const float* __restrict__ agg,
    const float* __restrict__ fw,  const float* __restrict__ fb,
    float* __restrict__ out)
{
    extern __shared__ float smf[];
    float* s_in = smf;            // 16 ci x 18 rows x stride 20 = 5760
    float* s_w2 = smf + 5760;     // 64 co x 144 duplicated pairs = 18432

    int b  = blockIdx.z;
    int x0 = blockIdx.x * 16, y0 = blockIdx.y * 16;
    int tid = threadIdx.x;
    int pl  = tid & 63;
    int cg  = tid >> 6;           // 8 co-groups of 8
    int r   = pl >> 2;            // output row 0..15
    int qd  = pl & 3;             // x-quad

    ull acc[2][8];
    #pragma unroll
    for (int kk = 0; kk < 2; kk++)
        #pragma unroll
        for (int j = 0; j < 8; j++) acc[kk][j] = 0ull;

    #pragma unroll 1
    for (int src = 0; src < 4; src++) {
        const float* ip = (src == 0) ? (sup + b*CHW_)
                                     : (agg + (src - 1)*(BB*CHW_) + b*CHW_);
        #pragma unroll 1
        for (int c0 = 0; c0 < 64; c0 += 16) {
            for (int e = tid; e < 16*324; e += 512) {
                int ci  = e / 324, rem = e % 324;
                int rr  = rem / 18, cc = rem % 18;
                int gy  = y0 - 1 + rr, gx = x0 - 1 + cc;
                float vv = 0.f;
                if (gy >= 0 && gy < HH && gx >= 0 && gx < WW)
                    vv = ip[(c0 + ci)*HW_ + gy*WW + gx];
                s_in[ci*360 + rr*20 + cc] = vv;
            }
            int cinb = src*64 + c0;
            for (int e = tid; e < 64*144; e += 512) {
                int co = e / 144, rem = e % 144;
                float wv = fw[co*2304 + cinb*9 + rem];
                s_w2[2*e] = wv; s_w2[2*e + 1] = wv;
            }
            __syncthreads();

            #pragma unroll 1
            for (int ci = 0; ci < 16; ci++) {
                const float* row = s_in + ci*360 + r*20 + qd*4;
                #pragma unroll
                for (int dy = 0; dy < 3; dy++) {
                    float2 P0 = *(const float2*)(row + dy*20 + 0);
                    float2 P1 = *(const float2*)(row + dy*20 + 2);
                    float2 P2 = *(const float2*)(row + dy*20 + 4);
                    ull A0 = pack2(P0.x, P0.y), B0 = pack2(P1.x, P1.y);
                    ull A1 = pack2(P0.y, P1.x), B1 = pack2(P1.y, P2.x);
                    ull A2 = B0,                B2 = pack2(P2.x, P2.y);
                    const float* wp = s_w2 + ((cg*8)*144 + ci*9 + dy*3)*2;
                    #pragma unroll
                    for (int j = 0; j < 8; j++) {
                        ull w0 = lds64f(wp + j*288 + 0);
                        fma2(acc[0][j], w0, A0);
                        fma2(acc[1][j], w0, B0);
                        ull w1 = lds64f(wp + j*288 + 2);
                        fma2(acc[0][j], w1, A1);
                        fma2(acc[1][j], w1, B1);
                        ull w2 = lds64f(wp + j*288 + 4);
                        fma2(acc[0][j], w2, A2);
                        fma2(acc[1][j], w2, B2);
                    }
                }
            }
            __syncthreads();
        }
    }

    int y = y0 + r, xb = x0 + qd*4;
    #pragma unroll
    for (int j = 0; j < 8; j++) {
        int co = cg*8 + j;
        float bv = fb[co];
        float2 lo = unpack2(acc[0][j]);
        float2 hi = unpack2(acc[1][j]);
        float4 o;
        o.x = fmaxf(lo.x + bv, 0.f);
        o.y = fmaxf(lo.y + bv, 0.f);
        o.z = fmaxf(hi.x + bv, 0.f);
        o.w = fmaxf(hi.y + bv, 0.f);
        *(float4*)&out[b*CHW_ + co*HW_ + y*WW + xb] = o;
    }
}

// ---------------- launch ----------------
static int natten_smem_bytes(int ks) {
    int r  = ks/2;
    int yr = 8 + 2*r, xr = 16 + 2*r;
    return (2*64*yr*xr + (2*ks - 1)*(2*ks - 1) + 2*128*ks*ks) * 4;
}

extern "C" void kernel_launch(void* const* d_in, const int* in_sizes, int n_in,
                              void* d_out, int out_size)
{
    const float* sup = (const float*)d_in[0];
    const float* key = (const float*)d_in[1];
    const float* csw = (const float*)d_in[2];
    const float* csb = (const float*)d_in[3];
    const float* crw = (const float*)d_in[4];
    const float* crb = (const float*)d_in[5];

    const float *vw[3], *vb[3], *rpb[3];
    if (in_sizes[8] == 25) {
        // dict-insertion (interleaved): v_w0, v_b0, rpb0, v_w1, v_b1, rpb1, ...
        for (int l = 0; l < 3; l++) {
            vw[l]  = (const float*)d_in[6 + 3*l];
            vb[l]  = (const float*)d_in[7 + 3*l];
            rpb[l] = (const float*)d_in[8 + 3*l];
        }
    } else {
        // signature order
        for (int l = 0; l < 3; l++) {
            vw[l]  = (const float*)d_in[6 + 2*l];
            vb[l]  = (const float*)d_in[7 + 2*l];
            rpb[l] = (const float*)d_in[12 + l];
        }
    }
    const float* fw = (const float*)d_in[15];
    const float* fb = (const float*)d_in[16];
    float* out = (float*)d_out;

    float *smoothp, *sup2p, *vp, *aggp;
    cudaGetSymbolAddress((void**)&smoothp, g_smooth);
    cudaGetSymbolAddress((void**)&sup2p,   g_sup2);
    cudaGetSymbolAddress((void**)&vp,      g_v);
    cudaGetSymbolAddress((void**)&aggp,    g_agg);

    cudaFuncSetAttribute(natten_kernel<3>, cudaFuncAttributeMaxDynamicSharedMemorySize, natten_smem_bytes(3));
    cudaFuncSetAttribute(natten_kernel<5>, cudaFuncAttributeMaxDynamicSharedMemorySize, natten_smem_bytes(5));
    cudaFuncSetAttribute(natten_kernel<7>, cudaFuncAttributeMaxDynamicSharedMemorySize, natten_smem_bytes(7));
    cudaFuncSetAttribute(fusion_kernel,    cudaFuncAttributeMaxDynamicSharedMemorySize, (5760 + 18432)*4);

    // 1. spatial shift + grouped smooth conv
    smooth_kernel<<<dim3(6, 6, BB*8), 256>>>(sup, csw, csb, smoothp);

    // 2. sup2 = 1x1 reduce over concat(sup, smooth)
    pw128_kernel<<<dim3(HW_/256, BB), 256>>>(sup, smoothp, crw, crb, sup2p);

    // 3. all three v convs in one launch, then fused NATTEN per level
    pw64x3_kernel<<<dim3(HW_/256, BB*3), 256>>>(sup2p,
        vw[0], vb[0], vw[1], vb[1], vw[2], vb[2], vp);

    natten_kernel<3><<<dim3(6, 12, BB), 256, natten_smem_bytes(3)>>>(
        key, sup2p, vp + 0*(BB*CHW_), rpb[0], aggp + 0*(BB*CHW_));
    natten_kernel<5><<<dim3(6, 12, BB), 256, natten_smem_bytes(5)>>>(
        key, sup2p, vp + 1*(BB*CHW_), rpb[1], aggp + 1*(BB*CHW_));
    natten_kernel<7><<<dim3(6, 12, BB), 256, natten_smem_bytes(7)>>>(
        key, sup2p, vp + 2*(BB*CHW_), rpb[2], aggp + 2*(BB*CHW_));

    // 4. fusion 3x3 + ReLU (packed f32x2, 512 threads)
    fusion_kernel<<<dim3(6, 6, BB), 512, (5760 + 18432)*4>>>(sup, aggp, fw, fb, out);
}

// round 12
// speedup vs baseline: 1.1721x; 1.0008x over previous
#include <cuda_runtime.h>

#define BB   4
#define CC_  64
#define HH   96
#define WW   96
#define HW_  (HH*WW)
#define CHW_ (CC_*HW_)

typedef unsigned long long ull;

// ---------------- packed f32x2 helpers ----------------
__device__ __forceinline__ ull pack2(float x, float y) {
    ull r; asm("mov.b64 %0, {%1, %2};" : "=l"(r) : "f"(x), "f"(y)); return r;
}
__device__ __forceinline__ float2 unpack2(ull v) {
    float2 t; asm("mov.b64 {%0, %1}, %2;" : "=f"(t.x), "=f"(t.y) : "l"(v)); return t;
}
__device__ __forceinline__ ull lds64f(const float* p) {
    ull r;
    asm("ld.shared.b64 %0, [%1];" : "=l"(r)
        : "l"((ull)__cvta_generic_to_shared(p)));
    return r;
}
__device__ __forceinline__ void lds128f(const float* p, ull& a, ull& b) {
    asm("ld.shared.v2.u64 {%0, %1}, [%2];" : "=l"(a), "=l"(b)
        : "l"((ull)__cvta_generic_to_shared(p)));
}
__device__ __forceinline__ void fma2(ull& d, ull a, ull b) {
    asm("fma.rn.f32x2 %0, %1, %2, %0;" : "+l"(d) : "l"(a), "l"(b));
}

// ---------------- scratch (static device globals; no allocation) ----------------
__device__ float g_smooth[BB*CHW_];
__device__ float g_sup2  [BB*CHW_];
__device__ float g_v     [3*BB*CHW_];
__device__ float g_agg   [3*BB*CHW_];

// shift table: sh in (-3,0,3) x sw in (-3,0,3) minus (0,0)
__constant__ int c_sh[8] = {-3,-3,-3, 0, 0, 3, 3, 3};
__constant__ int c_sw[8] = {-3, 0, 3,-3, 3,-3, 0, 3};

// ---------------- kernel 1: shift + grouped 3x3 conv (smooth) ----------------
__global__ __launch_bounds__(256) void smooth_kernel(
    const float* __restrict__ sup, const float* __restrict__ w,
    const float* __restrict__ bias, float* __restrict__ out)
{
    __shared__ float s_in[8*18*18];
    __shared__ float s_w [8*8*9];

    int bz = blockIdx.z;
    int g  = bz & 7;
    int b  = bz >> 3;
    int x0 = blockIdx.x * 16, y0 = blockIdx.y * 16;
    int sh = c_sh[g], sw = c_sw[g];
    int tid = threadIdx.x;

    for (int e = tid; e < 8*324; e += 256) {
        int ci = e / 324, rem = e % 324;
        int rr = rem / 18, cc = rem % 18;
        int sy = y0 - 1 + rr;
        int sx = x0 - 1 + cc;
        int gy = sy - sh;
        int gx = sx - sw;
        float v = 0.f;
        if (sy >= 0 && sy < HH && sx >= 0 && sx < WW &&
            gy >= 0 && gy < HH && gx >= 0 && gx < WW)
            v = sup[b*CHW_ + (g*8 + ci)*HW_ + gy*WW + gx];
        s_in[e] = v;
    }
    for (int e = tid; e < 576; e += 256) s_w[e] = w[g*8*72 + e];
    __syncthreads();

    int ty = tid >> 4, tx = tid & 15;
    float acc[8];
    #pragma unroll
    for (int j = 0; j < 8; j++) acc[j] = 0.f;

    #pragma unroll 1
    for (int ci = 0; ci < 8; ci++) {
        const float* base = s_in + ci*324 + ty*18 + tx;
        #pragma unroll
        for (int t = 0; t < 9; t++) {
            int dy = t / 3, dx = t % 3;
            float v = base[dy*18 + dx];
            #pragma unroll
            for (int co = 0; co < 8; co++)
                acc[co] = fmaf(s_w[co*72 + ci*9 + t], v, acc[co]);
        }
    }
    int y = y0 + ty, x = x0 + tx;
    #pragma unroll
    for (int co = 0; co < 8; co++)
        out[b*CHW_ + (g*8 + co)*HW_ + y*WW + x] = acc[co] + bias[g*8 + co];
}

// ---------------- kernel 2a: pointwise conv 1x1, CIN=128 ----------------
__global__ __launch_bounds__(256) void pw128_kernel(
    const float* __restrict__ inA, const float* __restrict__ inB,
    const float* __restrict__ wgt, const float* __restrict__ bias,
    float* __restrict__ out)
{
    __shared__ float s_in[16*256];
    __shared__ float s_w [64*16];

    int b  = blockIdx.y;
    int p0 = blockIdx.x * 256;
    int tid = threadIdx.x;
    int pl = tid & 63;
    int cg = tid >> 6;

    float acc[4][16];
    #pragma unroll
    for (int k = 0; k < 4; k++)
        #pragma unroll
        for (int j = 0; j < 16; j++) acc[k][j] = 0.f;

    for (int c0 = 0; c0 < 128; c0 += 16) {
        #pragma unroll
        for (int i = 0; i < 16; i++) {
            int e  = tid + i*256;
            int ci = c0 + (e >> 8);
            int px = e & 255;
            const float* src = (ci < 64) ? (inA + b*CHW_ + ci*HW_)
                                         : (inB + b*CHW_ + (ci - 64)*HW_);
            s_in[e] = src[p0 + px];
        }
        #pragma unroll
        for (int i = 0; i < 4; i++) {
            int e = tid + i*256;
            int co = e >> 4, ci = e & 15;
            s_w[e] = wgt[co*128 + c0 + ci];
        }
        __syncthreads();

        #pragma unroll 4
        for (int ci = 0; ci < 16; ci++) {
            float v0 = s_in[ci*256 + pl];
            float v1 = s_in[ci*256 + pl + 64];
            float v2 = s_in[ci*256 + pl + 128];
            float v3 = s_in[ci*256 + pl + 192];
            #pragma unroll
            for (int j = 0; j < 16; j++) {
                float wv = s_w[(cg*16 + j)*16 + ci];
                acc[0][j] = fmaf(wv, v0, acc[0][j]);
                acc[1][j] = fmaf(wv, v1, acc[1][j]);
                acc[2][j] = fmaf(wv, v2, acc[2][j]);
                acc[3][j] = fmaf(wv, v3, acc[3][j]);
            }
        }
        __syncthreads();
    }

    #pragma unroll
    for (int j = 0; j < 16; j++) {
        int co = cg*16 + j;
        float bv = bias[co];
        float* o = out + b*CHW_ + co*HW_ + p0;
        o[pl]       = acc[0][j] + bv;
        o[pl + 64]  = acc[1][j] + bv;
        o[pl + 128] = acc[2][j] + bv;
        o[pl + 192] = acc[3][j] + bv;
    }
}

// ---------------- kernel 2b: three 1x1 convs (64->64) in one launch ----------------
__global__ __launch_bounds__(256) void pw64x3_kernel(
    const float* __restrict__ inA,
    const float* __restrict__ w0, const float* __restrict__ b0,
    const float* __restrict__ w1, const float* __restrict__ b1,
    const float* __restrict__ w2, const float* __restrict__ b2,
    float* __restrict__ out)
{
    __shared__ float s_in[16*256];
    __shared__ float s_w [64*16];

    int lvl = blockIdx.y >> 2;
    int b   = blockIdx.y & 3;
    const float* wgt  = (lvl == 0) ? w0 : (lvl == 1) ? w1 : w2;
    const float* bias = (lvl == 0) ? b0 : (lvl == 1) ? b1 : b2;
    out += lvl * (BB*CHW_);

    int p0 = blockIdx.x * 256;
    int tid = threadIdx.x;
    int pl = tid & 63;
    int cg = tid >> 6;

    float acc[4][16];
    #pragma unroll
    for (int k = 0; k < 4; k++)
        #pragma unroll
        for (int j = 0; j < 16; j++) acc[k][j] = 0.f;

    for (int c0 = 0; c0 < 64; c0 += 16) {
        #pragma unroll
        for (int i = 0; i < 16; i++) {
            int e  = tid + i*256;
            int ci = c0 + (e >> 8);
            int px = e & 255;
            s_in[e] = inA[b*CHW_ + ci*HW_ + p0 + px];
        }
        #pragma unroll
        for (int i = 0; i < 4; i++) {
            int e = tid + i*256;
            int co = e >> 4, ci = e & 15;
            s_w[e] = wgt[co*64 + c0 + ci];
        }
        __syncthreads();

        #pragma unroll 4
        for (int ci = 0; ci < 16; ci++) {
            float v0 = s_in[ci*256 + pl];
            float v1 = s_in[ci*256 + pl + 64];
            float v2 = s_in[ci*256 + pl + 128];
            float v3 = s_in[ci*256 + pl + 192];
            #pragma unroll
            for (int j = 0; j < 16; j++) {
                float wv = s_w[(cg*16 + j)*16 + ci];
                acc[0][j] = fmaf(wv, v0, acc[0][j]);
                acc[1][j] = fmaf(wv, v1, acc[1][j]);
                acc[2][j] = fmaf(wv, v2, acc[2][j]);
                acc[3][j] = fmaf(wv, v3, acc[3][j]);
            }
        }
        __syncthreads();
    }

    #pragma unroll
    for (int j = 0; j < 16; j++) {
        int co = cg*16 + j;
        float bv = bias[co];
        float* o = out + b*CHW_ + co*HW_ + p0;
        o[pl]       = acc[0][j] + bv;
        o[pl + 64]  = acc[1][j] + bv;
        o[pl + 128] = acc[2][j] + bv;
        o[pl + 192] = acc[3][j] + bv;
    }
}

// ---------------- kernel 3: fused NATTEN, channel-split, 256 threads ----------------
// thread (h, px): h = warp-half (channels h*32..h*32+31), px = pixel.
// QK partials staged in s_part[2][128][KSQ]; after one barrier EVERY thread
// redundantly combines partials + rpb and does softmax in registers (no
// divergence, no write-back, no second barrier), then AV on own channels.
template<int KS>
__global__ __launch_bounds__(256) void natten_kernel(
    const float* __restrict__ q, const float* __restrict__ k,
    const float* __restrict__ v, const float* __restrict__ rpb,
    float* __restrict__ out)
{
    constexpr int R    = KS/2;
    constexpr int YR   = 8  + 2*R;
    constexpr int XR   = 16 + 2*R;
    constexpr int TILE = YR*XR;
    constexpr int KSQ  = KS*KS;
    constexpr int RPB  = 2*KS - 1;

    extern __shared__ float sm[];
    float* s_k    = sm;                   // 64*TILE floats (32 c2-pairs)
    float* s_v    = s_k + 64*TILE;
    float* s_rpb  = s_v + 64*TILE;
    float* s_part = s_rpb + RPB*RPB;      // [2][128][KSQ]

    int b  = blockIdx.z;
    int x0 = blockIdx.x * 16;
    int y0 = blockIdx.y * 8;
    int tid = threadIdx.x;
    int h   = tid >> 7;
    int px  = tid & 127;

    const float* kb = k + b*CHW_;
    const float* vb = v + b*CHW_;
    for (int e = tid; e < 32*TILE; e += 256) {
        int c2  = e / TILE;
        int rem = e % TILE;
        int yy  = rem / XR, xx = rem % XR;
        int gy  = y0 - R + yy, gx = x0 - R + xx;
        float k0 = 0.f, k1 = 0.f, v0 = 0.f, v1 = 0.f;
        if (gy >= 0 && gy < HH && gx >= 0 && gx < WW) {
            int base = (2*c2)*HW_ + gy*WW + gx;
            k0 = kb[base]; k1 = kb[base + HW_];
            v0 = vb[base]; v1 = vb[base + HW_];
        }
        s_k[2*e] = k0; s_k[2*e + 1] = k1;
        s_v[2*e] = v0; s_v[2*e + 1] = v1;
    }
    for (int e = tid; e < RPB*RPB; e += 256) s_rpb[e] = rpb[e];
    __syncthreads();

    int ty = px >> 4, tx = px & 15;
    int y = y0 + ty, x = x0 + tx;

    // q registers for this half's 16 channel-pairs
    ull q2[16];
    #pragma unroll
    for (int i = 0; i < 16; i++) {
        int c2 = h*16 + i;
        const float* qp = q + b*CHW_ + (2*c2)*HW_ + y*WW + x;
        q2[i] = pack2(qp[0], qp[HW_]);
    }

    int ni = min(max(y - R, 0), HH - KS);
    int nj = min(max(x - R, 0), WW - KS);
    int yy0 = ni - (y0 - R);
    int xx0 = nj - (x0 - R);
    int pi  = KS - 1 + ni - y;
    int pj  = KS - 1 + nj - x;

    // QK partial dots over this half's 32 channels (qq unrolled -> load MLP)
    #pragma unroll 1
    for (int p = 0; p < KS; p++) {
        #pragma unroll
        for (int qq = 0; qq < KS; qq++) {
            const float* kp = s_k + 2*((h*16)*TILE + (yy0 + p)*XR + xx0 + qq);
            ull s0 = 0ull, s1 = 0ull, s2 = 0ull, s3 = 0ull;
            #pragma unroll
            for (int i = 0; i < 16; i += 4) {
                fma2(s0, q2[i],     lds64f(kp + 2*(i    )*TILE));
                fma2(s1, q2[i + 1], lds64f(kp + 2*(i + 1)*TILE));
                fma2(s2, q2[i + 2], lds64f(kp + 2*(i + 2)*TILE));
                fma2(s3, q2[i + 3], lds64f(kp + 2*(i + 3)*TILE));
            }
            float2 ua = unpack2(s0), ub = unpack2(s1);
            float2 uc = unpack2(s2), ud = unpack2(s3);
            s_part[h*128*KSQ + px*KSQ + p*KS + qq] =
                ((ua.x + ua.y) + (ub.x + ub.y)) + ((uc.x + uc.y) + (ud.x + ud.y));
        }
    }
    __syncthreads();

    // every thread: combine partials + rpb, softmax in registers (redundant
    // across halves — removes divergence and a barrier)
    float ar[KSQ];
    float mx = -1e30f;
    #pragma unroll
    for (int t = 0; t < KSQ; t++) {
        int p = t / KS, qq = t % KS;
        float dot = s_part[px*KSQ + t] + s_part[128*KSQ + px*KSQ + t]
                  + s_rpb[(pi + p)*RPB + pj + qq];
        ar[t] = dot;
        mx = fmaxf(mx, dot);
    }
    float ssum = 0.f;
    #pragma unroll
    for (int t = 0; t < KSQ; t++) {
        float e = __expf(ar[t] - mx);
        ar[t] = e;
        ssum += e;
    }
    float inv = 1.0f / ssum;

    // AV over this half's 16 channel-pairs (qq unrolled)
    ull accv[16];
    #pragma unroll
    for (int i = 0; i < 16; i++) accv[i] = 0ull;
    #pragma unroll 1
    for (int p = 0; p < KS; p++) {
        #pragma unroll
        for (int qq = 0; qq < KS; qq++) {
            float av = ar[p*KS + qq] * inv;
            ull a2 = pack2(av, av);
            const float* vp = s_v + 2*((h*16)*TILE + (yy0 + p)*XR + xx0 + qq);
            #pragma unroll
            for (int i = 0; i < 16; i++)
                fma2(accv[i], a2, lds64f(vp + 2*i*TILE));
        }
    }
    float* ob = out + b*CHW_ + y*WW + x;
    #pragma unroll
    for (int i = 0; i < 16; i++) {
        float2 rv = unpack2(accv[i]);
        int c = 2*(h*16 + i);
        ob[c*HW_]       = rv.x;
        ob[(c + 1)*HW_] = rv.y;
    }
}

// ---------------- kernel 4: fusion 3x3 conv (256 -> 64) + ReLU, f32x2, 512 thr ----
// block: 16x16 px tile; thread: 4 x-adjacent px (quad) x 8 co, packed pairs.
// Weights in smem as [co][ci][tap(pad 10)] dup-pairs -> 9 taps fetched with
// 4x LDS.128 + 1x LDS.64 per (ci, co).
__global__ __launch_bounds__(512) void fusion_kernel(
    const float* __restrict__ sup, const float* __restrict__ agg,
    const float* __restrict__ fw,  const float* __restrict__ fb,
    float* __restrict__ out)
{
    extern __shared__ float smf[];
    float* s_in = smf;            // 16 ci x 18 rows x stride 20 = 5760
    float* s_w2 = smf + 5760;     // 64 co x 16 ci x 10 x 2 = 20480

    int b  = blockIdx.z;
    int x0 = blockIdx.x * 16, y0 = blockIdx.y * 16;
    int tid = threadIdx.x;
    int pl  = tid & 63;
    int cg  = tid >> 6;           // 8 co-groups of 8
    int r   = pl >> 2;            // output row 0..15
    int qd  = pl & 3;             // x-quad

    ull acc[2][8];
    #pragma unroll
    for (int kk = 0; kk < 2; kk++)
        #pragma unroll
        for (int j = 0; j < 8; j++) acc[kk][j] = 0ull;

    #pragma unroll 1
    for (int src = 0; src < 4; src++) {
        const float* ip = (src == 0) ? (sup + b*CHW_)
                                     : (agg + (src - 1)*(BB*CHW_) + b*CHW_);
        #pragma unroll 1
        for (int c0 = 0; c0 < 64; c0 += 16) {
            for (int e = tid; e < 16*324; e += 512) {
                int ci  = e / 324, rem = e % 324;
                int rr  = rem / 18, cc = rem % 18;
                int gy  = y0 - 1 + rr, gx = x0 - 1 + cc;
                float vv = 0.f;
                if (gy >= 0 && gy < HH && gx >= 0 && gx < WW)
                    vv = ip[(c0 + ci)*HW_ + gy*WW + gx];
                s_in[ci*360 + rr*20 + cc] = vv;
            }
            int cinb = src*64 + c0;
            for (int e = tid; e < 64*144; e += 512) {
                int co  = e / 144, rem = e % 144;
                int ci  = rem / 9, t = rem - ci*9;
                float wv = fw[co*2304 + cinb*9 + rem];
                int pos = 2*((co*16 + ci)*10 + t);
                s_w2[pos] = wv; s_w2[pos + 1] = wv;
            }
            __syncthreads();

            #pragma unroll 1
            for (int ci = 0; ci < 16; ci++) {
                const float* row = s_in + ci*360 + r*20 + qd*4;
                ull A[9], Bv[9];
                #pragma unroll
                for (int dy = 0; dy < 3; dy++) {
                    float2 P0 = *(const float2*)(row + dy*20 + 0);
                    float2 P1 = *(const float2*)(row + dy*20 + 2);
                    float2 P2 = *(const float2*)(row + dy*20 + 4);
                    A [dy*3 + 0] = pack2(P0.x, P0.y); Bv[dy*3 + 0] = pack2(P1.x, P1.y);
                    A [dy*3 + 1] = pack2(P0.y, P1.x); Bv[dy*3 + 1] = pack2(P1.y, P2.x);
                    A [dy*3 + 2] = pack2(P1.x, P1.y); Bv[dy*3 + 2] = pack2(P2.x, P2.y);
                }
                #pragma unroll
                for (int j = 0; j < 8; j++) {
                    const float* wp = s_w2 + 2*(((cg*8 + j)*16 + ci)*10);
                    ull wt[9];
                    lds128f(wp + 0,  wt[0], wt[1]);
                    lds128f(wp + 4,  wt[2], wt[3]);
                    lds128f(wp + 8,  wt[4], wt[5]);
                    lds128f(wp + 12, wt[6], wt[7]);
                    wt[8] = lds64f(wp + 16);
                    #pragma unroll
                    for (int t = 0; t < 9; t++) {
                        fma2(acc[0][j], wt[t], A[t]);
                        fma2(acc[1][j], wt[t], Bv[t]);
                    }
                }
            }
            __syncthreads();
        }
    }

    int y = y0 + r, xb = x0 + qd*4;
    #pragma unroll
    for (int j = 0; j < 8; j++) {
        int co = cg*8 + j;
        float bv = fb[co];
        float2 lo = unpack2(acc[0][j]);
        float2 hi = unpack2(acc[1][j]);
        float4 o;
        o.x = fmaxf(lo.x + bv, 0.f);
        o.y = fmaxf(lo.y + bv, 0.f);
        o.z = fmaxf(hi.x + bv, 0.f);
        o.w = fmaxf(hi.y + bv, 0.f);
        *(float4*)&out[b*CHW_ + co*HW_ + y*WW + xb] = o;
    }
}

// ---------------- launch ----------------
static int natten_smem_bytes(int ks) {
    int r  = ks/2;
    int yr = 8 + 2*r, xr = 16 + 2*r;
    return (2*64*yr*xr + (2*ks - 1)*(2*ks - 1) + 2*128*ks*ks) * 4;
}

extern "C" void kernel_launch(void* const* d_in, const int* in_sizes, int n_in,
                              void* d_out, int out_size)
{
    const float* sup = (const float*)d_in[0];
    const float* key = (const float*)d_in[1];
    const float* csw = (const float*)d_in[2];
    const float* csb = (const float*)d_in[3];
    const float* crw = (const float*)d_in[4];
    const float* crb = (const float*)d_in[5];

    const float *vw[3], *vb[3], *rpb[3];
    if (in_sizes[8] == 25) {
        // dict-insertion (interleaved): v_w0, v_b0, rpb0, v_w1, v_b1, rpb1, ...
        for (int l = 0; l < 3; l++) {
            vw[l]  = (const float*)d_in[6 + 3*l];
            vb[l]  = (const float*)d_in[7 + 3*l];
            rpb[l] = (const float*)d_in[8 + 3*l];
        }
    } else {
        // signature order
        for (int l = 0; l < 3; l++) {
            vw[l]  = (const float*)d_in[6 + 2*l];
            vb[l]  = (const float*)d_in[7 + 2*l];
            rpb[l] = (const float*)d_in[12 + l];
        }
    }
    const float* fw = (const float*)d_in[15];
    const float* fb = (const float*)d_in[16];
    float* out = (float*)d_out;

    float *smoothp, *sup2p, *vp, *aggp;
    cudaGetSymbolAddress((void**)&smoothp, g_smooth);
    cudaGetSymbolAddress((void**)&sup2p,   g_sup2);
    cudaGetSymbolAddress((void**)&vp,      g_v);
    cudaGetSymbolAddress((void**)&aggp,    g_agg);

    cudaFuncSetAttribute(natten_kernel<3>, cudaFuncAttributeMaxDynamicSharedMemorySize, natten_smem_bytes(3));
    cudaFuncSetAttribute(natten_kernel<5>, cudaFuncAttributeMaxDynamicSharedMemorySize, natten_smem_bytes(5));
    cudaFuncSetAttribute(natten_kernel<7>, cudaFuncAttributeMaxDynamicSharedMemorySize, natten_smem_bytes(7));
    cudaFuncSetAttribute(fusion_kernel,    cudaFuncAttributeMaxDynamicSharedMemorySize, (5760 + 20480)*4);

    // 1. spatial shift + grouped smooth conv
    smooth_kernel<<<dim3(6, 6, BB*8), 256>>>(sup, csw, csb, smoothp);

    // 2. sup2 = 1x1 reduce over concat(sup, smooth)
    pw128_kernel<<<dim3(HW_/256, BB), 256>>>(sup, smoothp, crw, crb, sup2p);

    // 3. all three v convs in one launch, then fused NATTEN per level
    pw64x3_kernel<<<dim3(HW_/256, BB*3), 256>>>(sup2p,
        vw[0], vb[0], vw[1], vb[1], vw[2], vb[2], vp);

    natten_kernel<3><<<dim3(6, 12, BB), 256, natten_smem_bytes(3)>>>(
        key, sup2p, vp + 0*(BB*CHW_), rpb[0], aggp + 0*(BB*CHW_));
    natten_kernel<5><<<dim3(6, 12, BB), 256, natten_smem_bytes(5)>>>(
        key, sup2p, vp + 1*(BB*CHW_), rpb[1], aggp + 1*(BB*CHW_));
    natten_kernel<7><<<dim3(6, 12, BB), 256, natten_smem_bytes(7)>>>(
        key, sup2p, vp + 2*(BB*CHW_), rpb[2], aggp + 2*(BB*CHW_));

    // 4. fusion 3x3 + ReLU (packed f32x2, 512 threads, LDS.128 weights)
    fusion_kernel<<<dim3(6, 6, BB), 512, (5760 + 20480)*4>>>(sup, aggp, fw, fb, out);
}